// round 17
// baseline (speedup 1.0000x reference)
#include <cuda_runtime.h>

#define C_CH   256
#define K_KERN 4
#define HID    64
#define HW     4096
#define B_MAX  32

__device__ float g_gap[B_MAX * C_CH];

// ---------------------------------------------------------------------------
// Kernel 1: pure global average pool per (b,c) plane. One block per plane.
// (Proven 24us form — byte-identical to the 77.9us baseline's gap.)
// ---------------------------------------------------------------------------
__global__ void __launch_bounds__(256) gap_kernel(const float* __restrict__ x) {
    const int bc = blockIdx.x;
    const float4* __restrict__ p = (const float4*)(x + (size_t)bc * HW);
    float s = 0.f;
#pragma unroll
    for (int i = 0; i < 4; i++) {
        float4 v = __ldg(&p[threadIdx.x + i * 256]);
        s += (v.x + v.y) + (v.z + v.w);
    }
#pragma unroll
    for (int o = 16; o > 0; o >>= 1) s += __shfl_down_sync(0xffffffffu, s, o);
    __shared__ float ws[8];
    const int lane = threadIdx.x & 31, w = threadIdx.x >> 5;
    if (lane == 0) ws[w] = s;
    __syncthreads();
    if (threadIdx.x == 0) {
        float t = 0.f;
#pragma unroll
        for (int i = 0; i < 8; i++) t += ws[i];
        g_gap[bc] = t * (1.0f / (float)HW);
    }
}

// ---------------------------------------------------------------------------
// Kernel 2: conv with PER-BLOCK redundant attention.
// Prologue: load g_gap[b,:] + compute fc1->relu->fc2->softmax in smem
// (~17K FMA, fc1_w L2-resident; latency hidden under other blocks' streaming).
// Body: depthwise 3x3 with effective filter, R14-proven form:
// strip = 16 rows per half-warp (ampl. 1.125x), 4 planes per 256-thread block
// (all same batch since 4 | 256), width-16 shuffle halo, evict-first stores,
// reversed plane order for L2 reuse of gap-streamed x tail.
// ---------------------------------------------------------------------------
__device__ __forceinline__ void load_row6(const float4* __restrict__ xp,
                                          int row, int sub, float* d) {
    float4 v;
    if ((unsigned)row < 64u) v = __ldg(&xp[row * 16 + sub]);
    else                     v = make_float4(0.f, 0.f, 0.f, 0.f);
    float l = __shfl_up_sync(0xffffffffu, v.w, 1, 16);
    float r = __shfl_down_sync(0xffffffffu, v.x, 1, 16);
    if (sub == 0)  l = 0.f;
    if (sub == 15) r = 0.f;
    d[0] = l; d[1] = v.x; d[2] = v.y; d[3] = v.z; d[4] = v.w; d[5] = r;
}

__global__ void __launch_bounds__(256) conv_kernel(const float* __restrict__ x,
                                                   const float* __restrict__ conv_w,
                                                   const float* __restrict__ fc1_w,
                                                   const float* __restrict__ fc1_b,
                                                   const float* __restrict__ fc2_w,
                                                   const float* __restrict__ fc2_b,
                                                   float* __restrict__ out) {
    const int tid  = threadIdx.x;
    const int lane = tid & 31;
    const int warp = tid >> 5;
    const int sub  = lane & 15;              // column group (0..15)
    const int gs   = warp * 2 + (lane >> 4); // half-warp id 0..15
    const int plane_local = gs >> 2;         // 0..3
    const int strip = gs & 3;                // 0..3 -> rows [strip*16, +16)

    const int grp = gridDim.x - 1 - blockIdx.x;   // reversed order
    const int bc = grp * 4 + plane_local;
    const int b = bc >> 8;                   // same for all 4 planes (4 | 256)
    const int c = bc & 255;

    // ---- per-block attention prologue (one batch per block) ----
    __shared__ float sg[C_CH];
    __shared__ float sh[HID];
    __shared__ float sattn[K_KERN];

    sg[tid] = g_gap[b * C_CH + tid];
    __syncthreads();

    if (tid < HID) {
        const float4* __restrict__ wr = (const float4*)(fc1_w + tid * C_CH);
        const float4* __restrict__ gg = (const float4*)sg;
        float acc = fc1_b[tid];
#pragma unroll 8
        for (int q = 0; q < C_CH / 4; q++) {
            float4 wv = __ldg(&wr[q]);
            float4 gv = gg[q];
            acc = fmaf(gv.x, wv.x, acc);
            acc = fmaf(gv.y, wv.y, acc);
            acc = fmaf(gv.z, wv.z, acc);
            acc = fmaf(gv.w, wv.w, acc);
        }
        sh[tid] = fmaxf(acc, 0.f);
    }
    __syncthreads();

    if (tid < K_KERN) {
        const float* __restrict__ wr = fc2_w + tid * HID;
        float acc = fc2_b[tid];
#pragma unroll 8
        for (int j = 0; j < HID; j++) acc = fmaf(sh[j], __ldg(&wr[j]), acc);
        sattn[tid] = acc;
    }
    __syncthreads();

    if (tid == 0) {
        float m = sattn[0];
#pragma unroll
        for (int k = 1; k < K_KERN; k++) m = fmaxf(m, sattn[k]);
        float e[K_KERN], ssum = 0.f;
#pragma unroll
        for (int k = 0; k < K_KERN; k++) { e[k] = expf(sattn[k] - m); ssum += e[k]; }
        const float inv = 1.0f / ssum;
#pragma unroll
        for (int k = 0; k < K_KERN; k++) sattn[k] = e[k] * inv;
    }
    __syncthreads();

    const float a0 = sattn[0];
    const float a1 = sattn[1];
    const float a2 = sattn[2];
    const float a3 = sattn[3];

    // ---- effective 9-tap filter for this half-warp's plane ----
    float w[9];
    const float* __restrict__ w0 = conv_w + (size_t)0 * C_CH * 9 + c * 9;
    const float* __restrict__ w1 = conv_w + (size_t)1 * C_CH * 9 + c * 9;
    const float* __restrict__ w2 = conv_w + (size_t)2 * C_CH * 9 + c * 9;
    const float* __restrict__ w3 = conv_w + (size_t)3 * C_CH * 9 + c * 9;
#pragma unroll
    for (int i = 0; i < 9; i++)
        w[i] = fmaf(a0, __ldg(&w0[i]),
               fmaf(a1, __ldg(&w1[i]),
               fmaf(a2, __ldg(&w2[i]), a3 * __ldg(&w3[i]))));

    const float4* __restrict__ xp = (const float4*)(x + (size_t)bc * HW);
    float4* __restrict__ op = (float4*)(out + (size_t)bc * HW);

    const int rbase = strip * 16;

    float rb[3][6];
    load_row6(xp, rbase - 1, sub, rb[0]);
    load_row6(xp, rbase,     sub, rb[1]);

#pragma unroll
    for (int rr = 0; rr < 16; rr++) {
        const int i0 = rr % 3;
        const int i1 = (rr + 1) % 3;
        const int i2 = (rr + 2) % 3;
        load_row6(xp, rbase + rr + 1, sub, rb[i2]);

        float4 o;
        float* ov = (float*)&o;
#pragma unroll
        for (int i = 0; i < 4; i++) {
            float acc;
            acc = rb[i0][i]     * w[0];
            acc = fmaf(rb[i0][i + 1], w[1], acc);
            acc = fmaf(rb[i0][i + 2], w[2], acc);
            acc = fmaf(rb[i1][i],     w[3], acc);
            acc = fmaf(rb[i1][i + 1], w[4], acc);
            acc = fmaf(rb[i1][i + 2], w[5], acc);
            acc = fmaf(rb[i2][i],     w[6], acc);
            acc = fmaf(rb[i2][i + 1], w[7], acc);
            acc = fmaf(rb[i2][i + 2], w[8], acc);
            ov[i] = acc;
        }
        __stcs(&op[(rbase + rr) * 16 + sub], o);
    }
}

// ---------------------------------------------------------------------------
extern "C" void kernel_launch(void* const* d_in, const int* in_sizes, int n_in,
                              void* d_out, int out_size) {
    const float* x      = (const float*)d_in[0];
    const float* conv_w = (const float*)d_in[1];
    const float* fc1_w  = (const float*)d_in[2];
    const float* fc1_b  = (const float*)d_in[3];
    const float* fc2_w  = (const float*)d_in[4];
    const float* fc2_b  = (const float*)d_in[5];
    float* out = (float*)d_out;

    const int B = in_sizes[0] / (C_CH * HW);   // 32

    gap_kernel<<<B * C_CH, 256>>>(x);
    conv_kernel<<<B * C_CH / 4, 256>>>(x, conv_w, fc1_w, fc1_b,
                                       fc2_w, fc2_b, out);
}